// round 1
// baseline (speedup 1.0000x reference)
#include <cuda_runtime.h>
#include <cstdint>
#include <cstddef>

#define NMAX 50000
#define DF   128
#define NC   64

// ---------------- scratch (static device globals; no allocation) -------------
__device__ float g_dinv[NMAX];          // degree, then rsqrt(degree)
__device__ float g_buf[(size_t)NMAX * DF]; // xw scratch (also used for 64-wide)
__device__ float g_h[(size_t)NMAX * DF];   // relu'd features
__device__ int   g_idx64;               // 1 if edge_index is int64, 0 if int32

// ---------------- edge dtype detection --------------------------------------
__global__ void k_detect(const void* edges) {
    if (threadIdx.x == 0 && blockIdx.x == 0) {
        const long long* p = (const long long*)edges;
        int ok = 1;
        #pragma unroll
        for (int i = 0; i < 16; i++) {
            long long v = p[i];
            if (v < 0 || v >= NMAX) ok = 0;
        }
        g_idx64 = ok;
    }
}

__device__ __forceinline__ int edge_at(const void* e, long long i, int is64) {
    return is64 ? (int)((const long long*)e)[i] : ((const int*)e)[i];
}

// ---------------- degree / normalization ------------------------------------
__global__ void k_deg_init(int n) {
    int i = blockIdx.x * blockDim.x + threadIdx.x;
    if (i < n) g_dinv[i] = 1.0f;   // self-loop
}

__global__ void k_deg_accum(const void* __restrict__ edges, long long E) {
    long long i = (long long)blockIdx.x * blockDim.x + threadIdx.x;
    if (i < E) {
        int is64 = g_idx64;
        int d = edge_at(edges, E + i, is64);
        atomicAdd(&g_dinv[d], 1.0f);
    }
}

__global__ void k_rsqrt(int n) {
    int i = blockIdx.x * blockDim.x + threadIdx.x;
    if (i < n) g_dinv[i] = rsqrtf(g_dinv[i]);
}

// ---------------- GEMM: Y[n,NOUT] = X[n,128] @ W[128,NOUT] -------------------
// Block tile: 128 rows x NOUT cols. 256 threads, each computes 4 rows x TN cols.
#define SXLD 132   // padded stride for X tile (avoid bank conflicts)

template<int NOUT>
__global__ void __launch_bounds__(256) k_gemm(const float* __restrict__ X,
                                              const float* __restrict__ W,
                                              float* __restrict__ Y, int n) {
    extern __shared__ float sm[];
    float* sW = sm;                 // 128 * NOUT
    float* sX = sm + 128 * NOUT;    // 128 * SXLD
    const int t = threadIdx.x;
    const int row0 = blockIdx.x * 128;

    // load W (whole 128 x NOUT) via float4
    for (int i = t * 4; i < 128 * NOUT; i += 1024)
        *(float4*)(sW + i) = *(const float4*)(W + i);

    // load X tile (128 rows x 128 cols) with padded stride
    for (int i = t * 4; i < 128 * 128; i += 1024) {
        int r = i >> 7, c = i & 127;
        int gr = row0 + r;
        float4 v = (gr < n) ? *(const float4*)(X + (size_t)gr * 128 + c)
                            : make_float4(0.f, 0.f, 0.f, 0.f);
        *(float4*)(sX + r * SXLD + c) = v;
    }
    __syncthreads();

    constexpr int TN = NOUT / 8;          // 16 (NOUT=128) or 8 (NOUT=64)
    const int rg = (t >> 3) * 4;          // row base within tile
    const int cg = (t & 7) * TN;          // col base

    float acc[4][TN];
    #pragma unroll
    for (int i = 0; i < 4; i++)
        #pragma unroll
        for (int j = 0; j < TN; j++) acc[i][j] = 0.f;

    #pragma unroll 8
    for (int k = 0; k < 128; k++) {
        float w[TN];
        #pragma unroll
        for (int j = 0; j < TN; j += 4)
            *(float4*)&w[j] = *(const float4*)(sW + k * NOUT + cg + j);
        #pragma unroll
        for (int i = 0; i < 4; i++) {
            float xv = sX[(rg + i) * SXLD + k];
            #pragma unroll
            for (int j = 0; j < TN; j++)
                acc[i][j] = fmaf(xv, w[j], acc[i][j]);
        }
    }

    #pragma unroll
    for (int i = 0; i < 4; i++) {
        int r = row0 + rg + i;
        if (r < n) {
            #pragma unroll
            for (int j = 0; j < TN; j += 4)
                *(float4*)(Y + (size_t)r * NOUT + cg + j) = *(float4*)&acc[i][j];
        }
    }
}

// ---------------- self-loop init: out = dinv^2 * xw + b ----------------------
template<int NOUT>
__global__ void k_selfinit(float* __restrict__ out, const float* __restrict__ b, int n) {
    long long i = (long long)blockIdx.x * blockDim.x + threadIdx.x; // float4 idx
    long long total = (long long)n * (NOUT / 4);
    if (i >= total) return;
    int row = (int)(i / (NOUT / 4));
    int c = (int)(i % (NOUT / 4)) * 4;
    float di = g_dinv[row];
    float norm = di * di;
    float4 v  = *(const float4*)(g_buf + (size_t)row * NOUT + c);
    float4 bb = *(const float4*)(b + c);
    float4 o;
    o.x = fmaf(norm, v.x, bb.x);
    o.y = fmaf(norm, v.y, bb.y);
    o.z = fmaf(norm, v.z, bb.z);
    o.w = fmaf(norm, v.w, bb.w);
    *(float4*)(out + (size_t)row * NOUT + c) = o;
}

// ---------------- edge scatter: out[dst] += norm * xw[src] -------------------
template<int NOUT>
__global__ void k_scatter(float* __restrict__ out, const void* __restrict__ edges,
                          long long E) {
    long long w = ((long long)blockIdx.x * blockDim.x + threadIdx.x) >> 5;
    int lane = threadIdx.x & 31;
    if (w >= E) return;
    int is64 = g_idx64;
    int s = edge_at(edges, w, is64);
    int d = edge_at(edges, E + w, is64);
    float norm = g_dinv[s] * g_dinv[d];
    if (NOUT == 128) {
        float4 v = *(const float4*)(g_buf + (size_t)s * 128 + lane * 4);
        float* p = out + (size_t)d * 128 + lane * 4;
        asm volatile("red.global.add.v4.f32 [%0], {%1,%2,%3,%4};"
                     :: "l"(p), "f"(v.x * norm), "f"(v.y * norm),
                        "f"(v.z * norm), "f"(v.w * norm) : "memory");
    } else {
        float2 v = *(const float2*)(g_buf + (size_t)s * 64 + lane * 2);
        float* p = out + (size_t)d * 64 + lane * 2;
        asm volatile("red.global.add.v2.f32 [%0], {%1,%2};"
                     :: "l"(p), "f"(v.x * norm), "f"(v.y * norm) : "memory");
    }
}

// ---------------- relu copy ---------------------------------------------------
__global__ void k_relu(const float* __restrict__ in, float* __restrict__ outv,
                       long long total4) {
    long long i = (long long)blockIdx.x * blockDim.x + threadIdx.x;
    if (i >= total4) return;
    float4 v = *(const float4*)(in + i * 4);
    v.x = fmaxf(v.x, 0.f); v.y = fmaxf(v.y, 0.f);
    v.z = fmaxf(v.z, 0.f); v.w = fmaxf(v.w, 0.f);
    *(float4*)(outv + i * 4) = v;
}

// ---------------- log_softmax over 64 cols (one warp per row) ----------------
__global__ void k_logsoftmax(const float* __restrict__ e3, float* __restrict__ logp,
                             int n) {
    long long w = ((long long)blockIdx.x * blockDim.x + threadIdx.x) >> 5;
    int lane = threadIdx.x & 31;
    if (w >= n) return;
    float v0 = e3[w * 64 + lane];
    float v1 = e3[w * 64 + 32 + lane];
    float m = fmaxf(v0, v1);
    #pragma unroll
    for (int o = 16; o; o >>= 1) m = fmaxf(m, __shfl_xor_sync(0xffffffffu, m, o));
    float s = expf(v0 - m) + expf(v1 - m);
    #pragma unroll
    for (int o = 16; o; o >>= 1) s += __shfl_xor_sync(0xffffffffu, s, o);
    float lz = m + logf(s);
    logp[w * 64 + lane] = v0 - lz;
    logp[w * 64 + 32 + lane] = v1 - lz;
}

// ---------------- launcher ----------------------------------------------------
extern "C" void kernel_launch(void* const* d_in, const int* in_sizes, int n_in,
                              void* d_out, int out_size) {
    const float* x  = (const float*)d_in[0];
    const void*  ed = d_in[1];
    const float* W1 = (const float*)d_in[2];
    const float* b1 = (const float*)d_in[3];
    const float* W2 = (const float*)d_in[4];
    const float* b2 = (const float*)d_in[5];
    const float* W3 = (const float*)d_in[6];
    const float* b3 = (const float*)d_in[7];

    int       N = in_sizes[0] / DF;
    long long E = (long long)in_sizes[1] / 2;

    float* out  = (float*)d_out;
    float* logp = out;
    float* e1   = out + (size_t)N * NC;
    float* e2   = e1 + (size_t)N * DF;
    float* e3   = e2 + (size_t)N * DF;

    float* buf; cudaGetSymbolAddress((void**)&buf, g_buf);
    float* h;   cudaGetSymbolAddress((void**)&h,   g_h);

    const int smem128 = (128 * 128 + 128 * SXLD) * 4;
    const int smem64  = (128 * 64  + 128 * SXLD) * 4;
    cudaFuncSetAttribute((const void*)k_gemm<128>,
                         cudaFuncAttributeMaxDynamicSharedMemorySize, smem128);
    cudaFuncSetAttribute((const void*)k_gemm<64>,
                         cudaFuncAttributeMaxDynamicSharedMemorySize, smem64);

    int nb_nodes  = (N + 255) / 256;
    int nb_edges  = (int)((E + 255) / 256);
    int nb_gemm   = (N + 127) / 128;
    long long tot128_4 = (long long)N * DF / 4;
    int nb_128v4  = (int)((tot128_4 + 255) / 256);
    long long tot64_4  = (long long)N * NC / 4;
    int nb_64v4   = (int)((tot64_4 + 255) / 256);
    int nb_scat   = (int)((E + 7) / 8);          // 8 warps (edges) per 256-thr block
    int nb_lsm    = (int)(((long long)N + 7) / 8);

    // degrees / normalization
    k_detect<<<1, 32>>>(ed);
    k_deg_init<<<nb_nodes, 256>>>(N);
    k_deg_accum<<<nb_edges, 256>>>(ed, E);
    k_rsqrt<<<nb_nodes, 256>>>(N);

    // ---- layer 1 ----
    k_gemm<128><<<nb_gemm, 256, smem128>>>(x, W1, buf, N);
    k_selfinit<128><<<nb_128v4, 256>>>(e1, b1, N);
    k_scatter<128><<<nb_scat, 256>>>(e1, ed, E);
    k_relu<<<nb_128v4, 256>>>(e1, h, tot128_4);

    // ---- layer 2 ----
    k_gemm<128><<<nb_gemm, 256, smem128>>>(h, W2, buf, N);
    k_selfinit<128><<<nb_128v4, 256>>>(e2, b2, N);
    k_scatter<128><<<nb_scat, 256>>>(e2, ed, E);
    k_relu<<<nb_128v4, 256>>>(e2, h, tot128_4);

    // ---- layer 3 ----
    k_gemm<64><<<nb_gemm, 256, smem64>>>(h, W3, buf, N);
    k_selfinit<64><<<nb_64v4, 256>>>(e3, b3, N);
    k_scatter<64><<<nb_scat, 256>>>(e3, ed, E);

    // log_softmax
    k_logsoftmax<<<nb_lsm, 256>>>(e3, logp, N);
}